// round 2
// baseline (speedup 1.0000x reference)
#include <cuda_runtime.h>
#include <cuda_bf16.h>
#include <cstddef>

// ---------------------------------------------------------------------------
// HyperNet: tiny CNN encoder -> FC -> VQ argmin -> q = emb[idx]
// then flat[b, :] = q[b] @ W_all   (rank-16 broadcast GEMM, HBM-bound)
// loss = 1.25 * mean((q - e)^2)    (q_lat and e_lat are value-identical)
// Output layout assumed: [B*T floats of flat][1 float loss]
// ---------------------------------------------------------------------------

#define BATCH 4

// scratch offsets (floats) inside one __device__ buffer (alloc-guard safe)
#define A1_OFF 0                       // 4*4*112*112 = 200704
#define A2_OFF 200704                  // 4*8*56*56   = 100352
#define A3_OFF 301056                  // 4*16*28*28  = 50176
#define A4_OFF 351232                  // 4*32*14*14  = 25088
#define A5_OFF 376320                  // 4*64*7*7    = 12544
#define BUF_TOTAL 388864

__device__ float g_buf[BUF_TOTAL];
__device__ float g_q[BATCH * 16];      // quantized codes, feeds projection

// ---------------------------------------------------------------------------
// Direct conv: kernel 4x4, stride 2, pad 1. One thread per output element.
// FIRST=true reads from the external rgb pointer, otherwise from g_buf+INOFF.
// ---------------------------------------------------------------------------
template <bool FIRST, int INOFF, int OUTOFF,
          int CIN, int COUT, int HIN, int WIN, int HOUT, int WOUT, bool ACT>
__global__ void conv_k(const float* __restrict__ in0,
                       const float* __restrict__ w,
                       const float* __restrict__ bias)
{
    const int total = BATCH * COUT * HOUT * WOUT;
    int idx = blockIdx.x * blockDim.x + threadIdx.x;
    if (idx >= total) return;

    int ox = idx % WOUT;
    int t  = idx / WOUT;
    int oy = t % HOUT;  t /= HOUT;
    int co = t % COUT;
    int b  = t / COUT;

    const float* in = FIRST ? in0 : (g_buf + INOFF);

    float s = bias[co];
    const int iy0 = oy * 2 - 1;
    const int ix0 = ox * 2 - 1;

    #pragma unroll 1
    for (int ci = 0; ci < CIN; ci++) {
        const float* ip = in + ((b * CIN + ci) * HIN) * WIN;
        const float* wp = w + ((co * CIN + ci) * 4) * 4;
        #pragma unroll
        for (int ky = 0; ky < 4; ky++) {
            int iy = iy0 + ky;
            if (iy < 0 || iy >= HIN) continue;
            const float* row = ip + iy * WIN;
            #pragma unroll
            for (int kx = 0; kx < 4; kx++) {
                int ix = ix0 + kx;
                if (ix < 0 || ix >= WIN) continue;
                s = fmaf(row[ix], wp[ky * 4 + kx], s);
            }
        }
    }
    if (ACT) s = (s >= 0.f) ? s : 0.01f * s;   // LeakyReLU(0.01)
    g_buf[OUTOFF + idx] = s;
}

// ---------------------------------------------------------------------------
// Head: AdaptiveAvgPool(1) -> fc1 (lrelu) -> fc2 -> VQ argmin -> q, loss
// Single block, 256 threads.
// ---------------------------------------------------------------------------
__global__ void head_k(const float* __restrict__ fc1w, const float* __restrict__ fc1b,
                       const float* __restrict__ fc2w, const float* __restrict__ fc2b,
                       const float* __restrict__ emb,
                       float* __restrict__ out, size_t loss_idx, int write_loss)
{
    __shared__ float pooled[BATCH * 64];
    __shared__ float h[BATCH * 16];
    __shared__ float e[BATCH * 16];
    __shared__ float perr[BATCH];

    int t = threadIdx.x;

    // pool: 256 (b,c) pairs, mean over 7x7
    {
        const float* p = g_buf + A5_OFF + t * 49;
        float s = 0.f;
        #pragma unroll
        for (int i = 0; i < 49; i++) s += p[i];
        pooled[t] = s * (1.f / 49.f);
    }
    __syncthreads();

    // fc1: 64 outputs, each a 64-dot; lrelu
    if (t < 64) {
        int b = t >> 4, j = t & 15;
        float s = fc1b[j];
        #pragma unroll
        for (int c = 0; c < 64; c++) s = fmaf(pooled[b * 64 + c], fc1w[j * 64 + c], s);
        h[t] = (s >= 0.f) ? s : 0.01f * s;
    }
    __syncthreads();

    // fc2: 64 outputs, each a 16-dot
    if (t < 64) {
        int b = t >> 4, j = t & 15;
        float s = fc2b[j];
        #pragma unroll
        for (int k = 0; k < 16; k++) s = fmaf(h[b * 16 + k], fc2w[j * 16 + k], s);
        e[t] = s;
    }
    __syncthreads();

    // VQ: per-batch argmin over 4 codes; q = emb[idx]; per-batch sq-error
    if (t < BATCH) {
        int b = t;
        float best = 3.402823466e+38f;
        int bi = 0;
        #pragma unroll
        for (int d = 0; d < 4; d++) {
            float dd = 0.f;
            #pragma unroll
            for (int k = 0; k < 16; k++) {
                float df = e[b * 16 + k] - emb[d * 16 + k];
                dd = fmaf(df, df, dd);
            }
            if (dd < best) { best = dd; bi = d; }   // first-min tiebreak == argmin
        }
        float se = 0.f;
        #pragma unroll
        for (int k = 0; k < 16; k++) {
            float qv = emb[bi * 16 + k];
            g_q[b * 16 + k] = qv;
            float df = qv - e[b * 16 + k];
            se = fmaf(df, df, se);
        }
        perr[b] = se;
    }
    __syncthreads();

    if (t == 0 && write_loss) {
        // loss = q_lat + 0.25*e_lat = 1.25 * mean((q-e)^2) over B*16 elems
        out[loss_idx] = 1.25f * (perr[0] + perr[1] + perr[2] + perr[3]) * (1.f / 64.f);
    }
}

// ---------------------------------------------------------------------------
// Projection: out[b, t] = sum_k q[b,k] * W[k, t].
// W rows start at k*T floats; T % 4 == 2 so only 8B alignment is guaranteed
// -> float2 loads/stores. One float2 column-pair per thread: 16 independent
// LDG.64 (MLP=16) + 4 STG.64. Pure HBM stream, 2.88 GB total traffic.
// ---------------------------------------------------------------------------
__global__ void proj_k(const float* __restrict__ W, float* __restrict__ out,
                       long long T)
{
    __shared__ float q[64];
    if (threadIdx.x < 64) q[threadIdx.x] = g_q[threadIdx.x];
    __syncthreads();

    long long T2 = T >> 1;
    long long i2 = (long long)blockIdx.x * blockDim.x + threadIdx.x;
    if (i2 < T2) {
        long long t = i2 * 2;
        float2 a0 = make_float2(0.f, 0.f);
        float2 a1 = a0, a2 = a0, a3 = a0;
        #pragma unroll
        for (int k = 0; k < 16; k++) {
            float2 w = *reinterpret_cast<const float2*>(W + (size_t)k * T + t);
            float q0 = q[k], q1 = q[16 + k], q2 = q[32 + k], q3 = q[48 + k];
            a0.x = fmaf(q0, w.x, a0.x); a0.y = fmaf(q0, w.y, a0.y);
            a1.x = fmaf(q1, w.x, a1.x); a1.y = fmaf(q1, w.y, a1.y);
            a2.x = fmaf(q2, w.x, a2.x); a2.y = fmaf(q2, w.y, a2.y);
            a3.x = fmaf(q3, w.x, a3.x); a3.y = fmaf(q3, w.y, a3.y);
        }
        *reinterpret_cast<float2*>(out + t)          = a0;
        *reinterpret_cast<float2*>(out + T + t)      = a1;
        *reinterpret_cast<float2*>(out + 2 * T + t)  = a2;
        *reinterpret_cast<float2*>(out + 3 * T + t)  = a3;
    }
    // odd-T tail (T is even for this problem; kept for safety)
    if (blockIdx.x == 0 && threadIdx.x == 0 && (T & 1)) {
        long long t = T - 1;
        #pragma unroll
        for (int b = 0; b < 4; b++) {
            float s = 0.f;
            for (int k = 0; k < 16; k++)
                s = fmaf(q[b * 16 + k], W[(size_t)k * T + t], s);
            out[(size_t)b * T + t] = s;
        }
    }
}

// ---------------------------------------------------------------------------
extern "C" void kernel_launch(void* const* d_in, const int* in_sizes, int n_in,
                              void* d_out, int out_size)
{
    const float* rgb   = (const float*)d_in[0];
    const float* cw1   = (const float*)d_in[1];
    const float* cb1   = (const float*)d_in[2];
    const float* cw2   = (const float*)d_in[3];
    const float* cb2   = (const float*)d_in[4];
    const float* cw3   = (const float*)d_in[5];
    const float* cb3   = (const float*)d_in[6];
    const float* cw4   = (const float*)d_in[7];
    const float* cb4   = (const float*)d_in[8];
    const float* cw5   = (const float*)d_in[9];
    const float* cb5   = (const float*)d_in[10];
    const float* fc1w  = (const float*)d_in[11];
    const float* fc1b  = (const float*)d_in[12];
    const float* fc2w  = (const float*)d_in[13];
    const float* fc2b  = (const float*)d_in[14];
    const float* emb   = (const float*)d_in[15];
    const float* W_all = (const float*)d_in[16];

    float* out = (float*)d_out;

    long long T = (long long)in_sizes[16] / 16;       // 35,968,706
    size_t flat_elems = (size_t)BATCH * (size_t)T;
    int write_loss = ((size_t)out_size > flat_elems) ? 1 : 0;

    // encoder convs (k4 s2 p1)
    conv_k<true , 0,      A1_OFF, 3,  4,  224, 224, 112, 112, true >
        <<<(BATCH*4*112*112 + 255) / 256, 256>>>(rgb, cw1, cb1);
    conv_k<false, A1_OFF, A2_OFF, 4,  8,  112, 112, 56,  56,  true >
        <<<(BATCH*8*56*56   + 255) / 256, 256>>>(nullptr, cw2, cb2);
    conv_k<false, A2_OFF, A3_OFF, 8,  16, 56,  56,  28,  28,  true >
        <<<(BATCH*16*28*28  + 255) / 256, 256>>>(nullptr, cw3, cb3);
    conv_k<false, A3_OFF, A4_OFF, 16, 32, 28,  28,  14,  14,  true >
        <<<(BATCH*32*14*14  + 255) / 256, 256>>>(nullptr, cw4, cb4);
    conv_k<false, A4_OFF, A5_OFF, 32, 64, 14,  14,  7,   7,   false>
        <<<(BATCH*64*7*7    + 255) / 256, 256>>>(nullptr, cw5, cb5);

    // pool + fc1 + fc2 + VQ + loss
    head_k<<<1, 256>>>(fc1w, fc1b, fc2w, fc2b, emb, out, flat_elems, write_loss);

    // rank-16 broadcast GEMM (the HBM-bound bulk of the problem)
    long long T2 = T >> 1;
    int nblk = (int)((T2 + 255) / 256);
    proj_k<<<nblk, 256>>>(W_all, out, T);
}

// round 3
// speedup vs baseline: 1.0457x; 1.0457x over previous
#include <cuda_runtime.h>
#include <cuda_bf16.h>
#include <cstddef>

// ---------------------------------------------------------------------------
// HyperNet: tiny CNN encoder -> FC -> VQ argmin -> q = emb[idx]
// then flat[b, :] = q[b] @ W_all   (rank-16 broadcast GEMM, HBM-bound)
// loss = 1.25 * mean((q - e)^2)
// ---------------------------------------------------------------------------

#define BATCH 4

// scratch offsets (floats) inside one __device__ buffer (alloc-guard safe)
#define A1_OFF 0                       // 4*4*112*112 = 200704
#define A2_OFF 200704                  // 4*8*56*56   = 100352
#define A3_OFF 301056                  // 4*16*28*28  = 50176
#define A4_OFF 351232                  // 4*32*14*14  = 25088
#define A5_OFF 376320                  // 4*64*7*7    = 12544
#define BUF_TOTAL 388864

__device__ float g_buf[BUF_TOTAL];
__device__ float g_q[BATCH * 16];      // quantized codes, feeds projection

// ---------------------------------------------------------------------------
// Direct conv: kernel 4x4, stride 2, pad 1.
// SPLIT consecutive threads cooperate on one output element, each covering
// CIN/SPLIT input channels, reduced via shfl_xor. Two accumulators break the
// serial FMA chain (ky 0/1 vs ky 2/3).
// ---------------------------------------------------------------------------
template <bool FIRST, int INOFF, int OUTOFF,
          int CIN, int COUT, int HIN, int WIN, int HOUT, int WOUT,
          bool ACT, int SPLIT>
__global__ void conv_k(const float* __restrict__ in0,
                       const float* __restrict__ w,
                       const float* __restrict__ bias)
{
    constexpr int CPT = CIN / SPLIT;                 // channels per thread
    const int total_thr = BATCH * COUT * HOUT * WOUT * SPLIT;
    int gt = blockIdx.x * blockDim.x + threadIdx.x;
    if (gt >= total_thr) return;

    int part = gt % SPLIT;
    int idx  = gt / SPLIT;

    int ox = idx % WOUT;
    int t  = idx / WOUT;
    int oy = t % HOUT;  t /= HOUT;
    int co = t % COUT;
    int b  = t / COUT;

    const float* in = FIRST ? in0 : (g_buf + INOFF);

    float s0 = 0.f, s1 = 0.f;
    const int iy0 = oy * 2 - 1;
    const int ix0 = ox * 2 - 1;
    const int ci0 = part * CPT;

    #pragma unroll
    for (int cc = 0; cc < CPT; cc++) {
        int ci = ci0 + cc;
        const float* ip = in + ((b * CIN + ci) * HIN) * WIN;
        const float* wp = w + ((co * CIN + ci) * 4) * 4;
        #pragma unroll
        for (int ky = 0; ky < 4; ky++) {
            int iy = iy0 + ky;
            if (iy < 0 || iy >= HIN) continue;
            const float* row = ip + iy * WIN;
            #pragma unroll
            for (int kx = 0; kx < 4; kx++) {
                int ix = ix0 + kx;
                if (ix < 0 || ix >= WIN) continue;
                if (ky < 2) s0 = fmaf(row[ix], wp[ky * 4 + kx], s0);
                else        s1 = fmaf(row[ix], wp[ky * 4 + kx], s1);
            }
        }
    }
    float s = s0 + s1;

    if constexpr (SPLIT > 1) {
        #pragma unroll
        for (int off = SPLIT / 2; off > 0; off >>= 1)
            s += __shfl_xor_sync(0xffffffffu, s, off);
    }

    if (part == 0) {
        s += bias[co];
        if (ACT) s = (s >= 0.f) ? s : 0.01f * s;     // LeakyReLU(0.01)
        g_buf[OUTOFF + idx] = s;
    }
}

// ---------------------------------------------------------------------------
// Head: AdaptiveAvgPool(1) -> fc1 (lrelu) -> fc2 -> VQ argmin -> q, loss
// Single block, 256 threads.
// ---------------------------------------------------------------------------
__global__ void head_k(const float* __restrict__ fc1w, const float* __restrict__ fc1b,
                       const float* __restrict__ fc2w, const float* __restrict__ fc2b,
                       const float* __restrict__ emb,
                       float* __restrict__ out, size_t loss_idx, int write_loss)
{
    __shared__ float pooled[BATCH * 64];
    __shared__ float h[BATCH * 16];
    __shared__ float e[BATCH * 16];
    __shared__ float perr[BATCH];

    int t = threadIdx.x;

    // pool: 256 (b,c) pairs, mean over 7x7
    {
        const float* p = g_buf + A5_OFF + t * 49;
        float s = 0.f;
        #pragma unroll
        for (int i = 0; i < 49; i++) s += p[i];
        pooled[t] = s * (1.f / 49.f);
    }
    __syncthreads();

    // fc1: 64 outputs, each a 64-dot; lrelu
    if (t < 64) {
        int b = t >> 4, j = t & 15;
        float s = fc1b[j];
        #pragma unroll
        for (int c = 0; c < 64; c++) s = fmaf(pooled[b * 64 + c], fc1w[j * 64 + c], s);
        h[t] = (s >= 0.f) ? s : 0.01f * s;
    }
    __syncthreads();

    // fc2: 64 outputs, each a 16-dot
    if (t < 64) {
        int b = t >> 4, j = t & 15;
        float s = fc2b[j];
        #pragma unroll
        for (int k = 0; k < 16; k++) s = fmaf(h[b * 16 + k], fc2w[j * 16 + k], s);
        e[t] = s;
    }
    __syncthreads();

    // VQ: per-batch argmin over 4 codes; q = emb[idx]; per-batch sq-error
    if (t < BATCH) {
        int b = t;
        float best = 3.402823466e+38f;
        int bi = 0;
        #pragma unroll
        for (int d = 0; d < 4; d++) {
            float dd = 0.f;
            #pragma unroll
            for (int k = 0; k < 16; k++) {
                float df = e[b * 16 + k] - emb[d * 16 + k];
                dd = fmaf(df, df, dd);
            }
            if (dd < best) { best = dd; bi = d; }   // first-min tiebreak == argmin
        }
        float se = 0.f;
        #pragma unroll
        for (int k = 0; k < 16; k++) {
            float qv = emb[bi * 16 + k];
            g_q[b * 16 + k] = qv;
            float df = qv - e[b * 16 + k];
            se = fmaf(df, df, se);
        }
        perr[b] = se;
    }
    __syncthreads();

    if (t == 0 && write_loss) {
        // loss = q_lat + 0.25*e_lat = 1.25 * mean((q-e)^2) over B*16 elems
        out[loss_idx] = 1.25f * (perr[0] + perr[1] + perr[2] + perr[3]) * (1.f / 64.f);
    }
}

// ---------------------------------------------------------------------------
// Projection: out[b, t] = sum_k q[b,k] * W[k, t].
// W rows start at k*T floats; T % 4 == 2 so only 8B alignment is guaranteed
// -> float2 loads/stores. 16 independent LDG.64 per thread (MLP=16).
// Pure HBM stream, 2.88 GB total traffic (at roofline already).
// ---------------------------------------------------------------------------
__global__ void proj_k(const float* __restrict__ W, float* __restrict__ out,
                       long long T)
{
    __shared__ float q[64];
    if (threadIdx.x < 64) q[threadIdx.x] = g_q[threadIdx.x];
    __syncthreads();

    long long T2 = T >> 1;
    long long i2 = (long long)blockIdx.x * blockDim.x + threadIdx.x;
    if (i2 < T2) {
        long long t = i2 * 2;
        float2 a0 = make_float2(0.f, 0.f);
        float2 a1 = a0, a2 = a0, a3 = a0;
        #pragma unroll
        for (int k = 0; k < 16; k++) {
            float2 w = *reinterpret_cast<const float2*>(W + (size_t)k * T + t);
            float q0 = q[k], q1 = q[16 + k], q2 = q[32 + k], q3 = q[48 + k];
            a0.x = fmaf(q0, w.x, a0.x); a0.y = fmaf(q0, w.y, a0.y);
            a1.x = fmaf(q1, w.x, a1.x); a1.y = fmaf(q1, w.y, a1.y);
            a2.x = fmaf(q2, w.x, a2.x); a2.y = fmaf(q2, w.y, a2.y);
            a3.x = fmaf(q3, w.x, a3.x); a3.y = fmaf(q3, w.y, a3.y);
        }
        *reinterpret_cast<float2*>(out + t)          = a0;
        *reinterpret_cast<float2*>(out + T + t)      = a1;
        *reinterpret_cast<float2*>(out + 2 * T + t)  = a2;
        *reinterpret_cast<float2*>(out + 3 * T + t)  = a3;
    }
    // odd-T tail (T is even for this problem; kept for safety)
    if (blockIdx.x == 0 && threadIdx.x == 0 && (T & 1)) {
        long long t = T - 1;
        #pragma unroll
        for (int b = 0; b < 4; b++) {
            float s = 0.f;
            for (int k = 0; k < 16; k++)
                s = fmaf(q[b * 16 + k], W[(size_t)k * T + t], s);
            out[(size_t)b * T + t] = s;
        }
    }
}

// ---------------------------------------------------------------------------
extern "C" void kernel_launch(void* const* d_in, const int* in_sizes, int n_in,
                              void* d_out, int out_size)
{
    const float* rgb   = (const float*)d_in[0];
    const float* cw1   = (const float*)d_in[1];
    const float* cb1   = (const float*)d_in[2];
    const float* cw2   = (const float*)d_in[3];
    const float* cb2   = (const float*)d_in[4];
    const float* cw3   = (const float*)d_in[5];
    const float* cb3   = (const float*)d_in[6];
    const float* cw4   = (const float*)d_in[7];
    const float* cb4   = (const float*)d_in[8];
    const float* cw5   = (const float*)d_in[9];
    const float* cb5   = (const float*)d_in[10];
    const float* fc1w  = (const float*)d_in[11];
    const float* fc1b  = (const float*)d_in[12];
    const float* fc2w  = (const float*)d_in[13];
    const float* fc2b  = (const float*)d_in[14];
    const float* emb   = (const float*)d_in[15];
    const float* W_all = (const float*)d_in[16];

    float* out = (float*)d_out;

    long long T = (long long)in_sizes[16] / 16;       // 35,968,706
    size_t flat_elems = (size_t)BATCH * (size_t)T;
    int write_loss = ((size_t)out_size > flat_elems) ? 1 : 0;

    // encoder convs (k4 s2 p1), channel-split for latency hiding
    {   // conv1: 3->4, 224->112, SPLIT=1 (200704 threads)
        int thr = BATCH*4*112*112;
        conv_k<true , 0,      A1_OFF, 3,  4,  224, 224, 112, 112, true , 1>
            <<<(thr + 255) / 256, 256>>>(rgb, cw1, cb1);
    }
    {   // conv2: 4->8, 112->56, SPLIT=2 (200704 threads)
        int thr = BATCH*8*56*56*2;
        conv_k<false, A1_OFF, A2_OFF, 4,  8,  112, 112, 56,  56,  true , 2>
            <<<(thr + 255) / 256, 256>>>(nullptr, cw2, cb2);
    }
    {   // conv3: 8->16, 56->28, SPLIT=4 (200704 threads)
        int thr = BATCH*16*28*28*4;
        conv_k<false, A2_OFF, A3_OFF, 8,  16, 56,  56,  28,  28,  true , 4>
            <<<(thr + 255) / 256, 256>>>(nullptr, cw3, cb3);
    }
    {   // conv4: 16->32, 28->14, SPLIT=8 (200704 threads)
        int thr = BATCH*32*14*14*8;
        conv_k<false, A3_OFF, A4_OFF, 16, 32, 28,  28,  14,  14,  true , 8>
            <<<(thr + 255) / 256, 256>>>(nullptr, cw4, cb4);
    }
    {   // conv5: 32->64, 14->7, SPLIT=8 (100352 threads)
        int thr = BATCH*64*7*7*8;
        conv_k<false, A4_OFF, A5_OFF, 32, 64, 14,  14,  7,   7,   false, 8>
            <<<(thr + 255) / 256, 256>>>(nullptr, cw5, cb5);
    }

    // pool + fc1 + fc2 + VQ + loss
    head_k<<<1, 256>>>(fc1w, fc1b, fc2w, fc2b, emb, out, flat_elems, write_loss);

    // rank-16 broadcast GEMM (the HBM-bound bulk of the problem)
    long long T2 = T >> 1;
    int nblk = (int)((T2 + 255) / 256);
    proj_k<<<nblk, 256>>>(W_all, out, T);
}